// round 1
// baseline (speedup 1.0000x reference)
#include <cuda_runtime.h>

#define NT0 7
#define NT1 24
#define NT2 288
#define NTP 2048
#define DM  512
#define BB  32
#define PP  2048

#define O0 0
#define O1 (NT0*DM)
#define O2 ((NT0+NT1)*DM)
#define O3 ((NT0+NT1+NT2)*DM)
#define TAB_FLOATS ((NT0+NT1+NT2+NTP)*DM)

// Scratch: factored lookup tables T0,T1,T2,Tp (~4.85 MB)
__device__ __align__(16) float g_tab[TAB_FLOATS];

// ---------------------------------------------------------------------------
// Kernel 1: build tables. One fused GEMM over 4 (src, W-block) batches.
// grid.x = 39 row-tiles (1 emb0 + 1 emb1 + 5 emb2 + 32 pe), grid.y = 8 col-tiles.
// Block 256 threads, 64x64 output tile, 4x4 per-thread micro-tile, K-chunks of 16.
// ---------------------------------------------------------------------------
__global__ void table_gemm_kernel(const float* __restrict__ emb0,
                                  const float* __restrict__ emb1,
                                  const float* __restrict__ emb2,
                                  const float* __restrict__ pe,
                                  const float* __restrict__ W,
                                  const float* __restrict__ bias) {
    __shared__ __align__(16) float As[64][16];
    __shared__ __align__(16) float Bs[16][64];

    const int bt = blockIdx.x;
    const float* src;
    float* dst;
    int M, rowBase, wRow, addB;
    if (bt == 0)      { src = emb0; M = NT0; rowBase = 0;           wRow = 0;     dst = g_tab + O0; addB = 0; }
    else if (bt == 1) { src = emb1; M = NT1; rowBase = 0;           wRow = DM;    dst = g_tab + O1; addB = 0; }
    else if (bt < 7)  { src = emb2; M = NT2; rowBase = (bt-2)*64;   wRow = 2*DM;  dst = g_tab + O2; addB = 0; }
    else              { src = pe;   M = NTP; rowBase = (bt-7)*64;   wRow = 3*DM;  dst = g_tab + O3; addB = 1; }

    const int tid = threadIdx.x;
    const int colBase = blockIdx.y * 64;
    const int tx = tid & 15, ty = tid >> 4;
    const int r0 = ty * 4, c0 = tx * 4;

    // load assignments
    const int ar = tid >> 2;           // A row 0..63
    const int ak = (tid & 3) * 4;      // A k   0,4,8,12
    const int bk = tid >> 4;           // B k   0..15
    const int bc = (tid & 15) * 4;     // B col 0..60

    float acc[4][4] = {};

    for (int k0 = 0; k0 < DM; k0 += 16) {
        float4 av = make_float4(0.f, 0.f, 0.f, 0.f);
        if (rowBase + ar < M)
            av = *reinterpret_cast<const float4*>(src + (size_t)(rowBase + ar) * DM + k0 + ak);
        As[ar][ak + 0] = av.x; As[ar][ak + 1] = av.y;
        As[ar][ak + 2] = av.z; As[ar][ak + 3] = av.w;

        float4 bv = *reinterpret_cast<const float4*>(W + (size_t)(wRow + k0 + bk) * DM + colBase + bc);
        *reinterpret_cast<float4*>(&Bs[bk][bc]) = bv;

        __syncthreads();

        #pragma unroll
        for (int kk = 0; kk < 16; kk++) {
            float a0 = As[r0 + 0][kk];
            float a1 = As[r0 + 1][kk];
            float a2 = As[r0 + 2][kk];
            float a3 = As[r0 + 3][kk];
            float4 b4 = *reinterpret_cast<const float4*>(&Bs[kk][c0]);
            acc[0][0] += a0 * b4.x; acc[0][1] += a0 * b4.y; acc[0][2] += a0 * b4.z; acc[0][3] += a0 * b4.w;
            acc[1][0] += a1 * b4.x; acc[1][1] += a1 * b4.y; acc[1][2] += a1 * b4.z; acc[1][3] += a1 * b4.w;
            acc[2][0] += a2 * b4.x; acc[2][1] += a2 * b4.y; acc[2][2] += a2 * b4.z; acc[2][3] += a2 * b4.w;
            acc[3][0] += a3 * b4.x; acc[3][1] += a3 * b4.y; acc[3][2] += a3 * b4.z; acc[3][3] += a3 * b4.w;
        }
        __syncthreads();
    }

    float bb0 = 0.f, bb1 = 0.f, bb2 = 0.f, bb3 = 0.f;
    if (addB) {
        bb0 = bias[colBase + c0 + 0];
        bb1 = bias[colBase + c0 + 1];
        bb2 = bias[colBase + c0 + 2];
        bb3 = bias[colBase + c0 + 3];
    }
    #pragma unroll
    for (int i = 0; i < 4; i++) {
        int row = rowBase + r0 + i;
        if (row < M) {
            float4 o;
            o.x = acc[i][0] + bb0;
            o.y = acc[i][1] + bb1;
            o.z = acc[i][2] + bb2;
            o.w = acc[i][3] + bb3;
            *reinterpret_cast<float4*>(dst + (size_t)row * DM + colBase + c0) = o;
        }
    }
}

// ---------------------------------------------------------------------------
// Kernel 2: gather-add. One block per position l (2048 blocks), 128 threads.
// Thread t owns columns [4t, 4t+4). Tp[l] hoisted to registers; the 64
// (stream,batch) index triples staged in smem; T0/T1/T2 rows read from
// global (L1/L2-resident: tables total 4.85 MB).
// ---------------------------------------------------------------------------
__global__ void gather_kernel(const int* __restrict__ in0, const int* __restrict__ tg0,
                              const int* __restrict__ in1, const int* __restrict__ tg1,
                              const int* __restrict__ in2, const int* __restrict__ tg2,
                              float* __restrict__ out) {
    const int l = blockIdx.x;      // 0..2047
    const int t = threadIdx.x;     // 0..127

    __shared__ int s0[64], s1[64], s2[64];
    if (t < 64) {
        int s = t >> 5, b = t & 31;
        int off = b * PP + l;
        s0[t] = (s ? tg0 : in0)[off];
        s1[t] = (s ? tg1 : in1)[off];
        s2[t] = (s ? tg2 : in2)[off];
    }

    const float4 tp = *reinterpret_cast<const float4*>(g_tab + O3 + (size_t)l * DM + 4 * t);

    __syncthreads();

    float4* outv = reinterpret_cast<float4*>(out);

    #pragma unroll 4
    for (int p = 0; p < 64; p++) {
        const float4 v0 = *reinterpret_cast<const float4*>(g_tab + O0 + (size_t)s0[p] * DM + 4 * t);
        const float4 v1 = *reinterpret_cast<const float4*>(g_tab + O1 + (size_t)s1[p] * DM + 4 * t);
        const float4 v2 = *reinterpret_cast<const float4*>(g_tab + O2 + (size_t)s2[p] * DM + 4 * t);
        float4 o;
        o.x = v0.x + v1.x + v2.x + tp.x;
        o.y = v0.y + v1.y + v2.y + tp.y;
        o.z = v0.z + v1.z + v2.z + tp.z;
        o.w = v0.w + v1.w + v2.w + tp.w;
        outv[(size_t)(p * PP + l) * (DM / 4) + t] = o;
    }
}

extern "C" void kernel_launch(void* const* d_in, const int* in_sizes, int n_in,
                              void* d_out, int out_size) {
    const int*   in0  = (const int*)d_in[0];
    const int*   tg0  = (const int*)d_in[1];
    const int*   in1  = (const int*)d_in[2];
    const int*   tg1  = (const int*)d_in[3];
    const int*   in2  = (const int*)d_in[4];
    const int*   tg2  = (const int*)d_in[5];
    const float* emb0 = (const float*)d_in[6];
    const float* emb1 = (const float*)d_in[7];
    const float* emb2 = (const float*)d_in[8];
    const float* pe   = (const float*)d_in[9];
    const float* W    = (const float*)d_in[10];
    const float* bias = (const float*)d_in[11];
    float* out = (float*)d_out;

    dim3 ggrid(39, 8);
    table_gemm_kernel<<<ggrid, 256>>>(emb0, emb1, emb2, pe, W, bias);
    gather_kernel<<<2048, 128>>>(in0, tg0, in1, tg1, in2, tg2, out);
}

// round 2
// speedup vs baseline: 1.0236x; 1.0236x over previous
#include <cuda_runtime.h>

#define NT0 7
#define NT1 24
#define NT2 288
#define NTP 2048
#define DM  512
#define BB  32
#define PP  2048

// table layout in scratch
#define OT0  0
#define OT1  (NT0*DM)                      // 7
#define OT01 ((NT0+NT1)*DM)                // 31
#define OT2  ((NT0+NT1+168)*DM)            // 199
#define OTP  ((NT0+NT1+168+NT2)*DM)        // 487
#define TAB_FLOATS ((NT0+NT1+168+NT2+NTP)*DM)

__device__ __align__(16) float g_tab[TAB_FLOATS];

// ---------------- f32x2 helpers ----------------
__device__ __forceinline__ unsigned long long pack2dup(float v) {
    unsigned long long r;
    asm("mov.b64 %0, {%1, %1};" : "=l"(r) : "f"(v));
    return r;
}
__device__ __forceinline__ void fma2(unsigned long long& d, unsigned long long a, unsigned long long b) {
    asm("fma.rn.f32x2 %0, %1, %2, %3;" : "=l"(d) : "l"(a), "l"(b), "l"(d));
}
__device__ __forceinline__ float2 unpack2(unsigned long long v) {
    float2 r;
    asm("mov.b64 {%0, %1}, %2;" : "=f"(r.x), "=f"(r.y) : "l"(v));
    return r;
}

// ---------------------------------------------------------------------------
// Kernel 1: table GEMM with FFMA2.
// Tile 64 rows x 32 cols, 64 threads, micro 8x4 (row-paired f32x2 accums).
// grid = (39 row-tiles, 16 col-tiles) = 624 blocks. K-chunk 16, double-buffered.
// Batches: bt0=emb0(7), bt1=emb1(24), bt2-6=emb2(288), bt7-38=pe(2048,+bias).
// ---------------------------------------------------------------------------
__global__ __launch_bounds__(64) void table_gemm_kernel(
        const float* __restrict__ emb0, const float* __restrict__ emb1,
        const float* __restrict__ emb2, const float* __restrict__ pe,
        const float* __restrict__ W,    const float* __restrict__ bias) {
    __shared__ __align__(16) float As[2][16][64];   // transposed: [k][row]
    __shared__ __align__(16) float Bs[2][16][32];   // [k][col]

    const int bt = blockIdx.x;
    const float* src;
    float* dst;
    int M, rowBase, wRow, addB;
    if (bt == 0)      { src = emb0; M = NT0; rowBase = 0;         wRow = 0;    dst = g_tab + OT0; addB = 0; }
    else if (bt == 1) { src = emb1; M = NT1; rowBase = 0;         wRow = DM;   dst = g_tab + OT1; addB = 0; }
    else if (bt < 7)  { src = emb2; M = NT2; rowBase = (bt-2)*64; wRow = 2*DM; dst = g_tab + OT2; addB = 0; }
    else              { src = pe;   M = NTP; rowBase = (bt-7)*64; wRow = 3*DM; dst = g_tab + OTP; addB = 1; }

    const int tid = threadIdx.x;            // 0..63
    const int ty8 = (tid >> 3) * 8;         // row offset 0..56
    const int tx4 = (tid & 7) * 4;          // col offset 0..28
    const int colBase = blockIdx.y * 32;

    const int arow = rowBase + tid;
    const bool aok = (arow < M);
    const float* aptr = src + (size_t)arow * DM;

    // B load indices (2 float4 per thread per chunk)
    const int lin0 = tid,        kb0 = lin0 >> 3, cb0 = (lin0 & 7) * 4;
    const int lin1 = 64 + tid,   kb1 = lin1 >> 3, cb1 = (lin1 & 7) * 4;
    const float* wbase = W + (size_t)wRow * DM + colBase;

    unsigned long long acc[4][4];
    #pragma unroll
    for (int i = 0; i < 4; i++)
        #pragma unroll
        for (int c = 0; c < 4; c++) acc[i][c] = 0ull;

    float4 pa[4], pb0, pb1;

    // prefetch chunk 0
    {
        #pragma unroll
        for (int j = 0; j < 4; j++)
            pa[j] = aok ? *reinterpret_cast<const float4*>(aptr + 4*j)
                        : make_float4(0.f,0.f,0.f,0.f);
        pb0 = *reinterpret_cast<const float4*>(wbase + (size_t)kb0 * DM + cb0);
        pb1 = *reinterpret_cast<const float4*>(wbase + (size_t)kb1 * DM + cb1);
    }
    // store chunk 0
    {
        #pragma unroll
        for (int j = 0; j < 4; j++) {
            As[0][4*j+0][tid] = pa[j].x; As[0][4*j+1][tid] = pa[j].y;
            As[0][4*j+2][tid] = pa[j].z; As[0][4*j+3][tid] = pa[j].w;
        }
        *reinterpret_cast<float4*>(&Bs[0][kb0][cb0]) = pb0;
        *reinterpret_cast<float4*>(&Bs[0][kb1][cb1]) = pb1;
    }
    __syncthreads();

    #pragma unroll 1
    for (int ch = 0; ch < 32; ch++) {
        const int buf = ch & 1;
        if (ch < 31) {
            const int k0 = (ch + 1) * 16;
            #pragma unroll
            for (int j = 0; j < 4; j++)
                pa[j] = aok ? *reinterpret_cast<const float4*>(aptr + k0 + 4*j)
                            : make_float4(0.f,0.f,0.f,0.f);
            pb0 = *reinterpret_cast<const float4*>(wbase + (size_t)(k0 + kb0) * DM + cb0);
            pb1 = *reinterpret_cast<const float4*>(wbase + (size_t)(k0 + kb1) * DM + cb1);
        }

        #pragma unroll
        for (int kk = 0; kk < 16; kk++) {
            ulonglong2 aA = *reinterpret_cast<const ulonglong2*>(&As[buf][kk][ty8]);
            ulonglong2 aB = *reinterpret_cast<const ulonglong2*>(&As[buf][kk][ty8 + 4]);
            float4 bv = *reinterpret_cast<const float4*>(&Bs[buf][kk][tx4]);
            unsigned long long a2[4] = {aA.x, aA.y, aB.x, aB.y};
            unsigned long long bd0 = pack2dup(bv.x);
            unsigned long long bd1 = pack2dup(bv.y);
            unsigned long long bd2 = pack2dup(bv.z);
            unsigned long long bd3 = pack2dup(bv.w);
            #pragma unroll
            for (int i = 0; i < 4; i++) {
                fma2(acc[i][0], a2[i], bd0);
                fma2(acc[i][1], a2[i], bd1);
                fma2(acc[i][2], a2[i], bd2);
                fma2(acc[i][3], a2[i], bd3);
            }
        }

        if (ch < 31) {
            const int nb = buf ^ 1;
            #pragma unroll
            for (int j = 0; j < 4; j++) {
                As[nb][4*j+0][tid] = pa[j].x; As[nb][4*j+1][tid] = pa[j].y;
                As[nb][4*j+2][tid] = pa[j].z; As[nb][4*j+3][tid] = pa[j].w;
            }
            *reinterpret_cast<float4*>(&Bs[nb][kb0][cb0]) = pb0;
            *reinterpret_cast<float4*>(&Bs[nb][kb1][cb1]) = pb1;
            __syncthreads();
        }
    }

    float4 bb = make_float4(0.f,0.f,0.f,0.f);
    if (addB)
        bb = *reinterpret_cast<const float4*>(bias + colBase + tx4);

    #pragma unroll
    for (int i = 0; i < 4; i++) {
        float2 u0 = unpack2(acc[i][0]);
        float2 u1 = unpack2(acc[i][1]);
        float2 u2 = unpack2(acc[i][2]);
        float2 u3 = unpack2(acc[i][3]);
        int re = rowBase + ty8 + 2*i;
        if (re < M) {
            float4 o = make_float4(u0.x + bb.x, u1.x + bb.y, u2.x + bb.z, u3.x + bb.w);
            *reinterpret_cast<float4*>(dst + (size_t)re * DM + colBase + tx4) = o;
        }
        if (re + 1 < M) {
            float4 o = make_float4(u0.y + bb.x, u1.y + bb.y, u2.y + bb.z, u3.y + bb.w);
            *reinterpret_cast<float4*>(dst + (size_t)(re + 1) * DM + colBase + tx4) = o;
        }
    }
}

// ---------------------------------------------------------------------------
// Kernel 2: fuse T01[i*24+j] = T0[i] + T1[j].  168 rows.
// ---------------------------------------------------------------------------
__global__ void fuse01_kernel() {
    const int r = blockIdx.x;          // 0..167
    const int i = r / 24, j = r % 24;
    const int t = threadIdx.x;         // 0..127
    float4 a = *reinterpret_cast<const float4*>(g_tab + OT0 + (size_t)i * DM + 4 * t);
    float4 b = *reinterpret_cast<const float4*>(g_tab + OT1 + (size_t)j * DM + 4 * t);
    float4 o = make_float4(a.x + b.x, a.y + b.y, a.z + b.z, a.w + b.w);
    *reinterpret_cast<float4*>(g_tab + OT01 + (size_t)r * DM + 4 * t) = o;
}

// ---------------------------------------------------------------------------
// Kernel 3: gather-add. 256 threads = 2 positions/block, grid 1024.
// out[token] = T01[i0*24+i1] + T2[i2] + Tp[l]
// ---------------------------------------------------------------------------
__global__ void gather_kernel(const int* __restrict__ in0, const int* __restrict__ tg0,
                              const int* __restrict__ in1, const int* __restrict__ tg1,
                              const int* __restrict__ in2, const int* __restrict__ tg2,
                              float* __restrict__ out) {
    const int t = threadIdx.x;
    const int half = t >> 7;           // which position
    const int lane = t & 127;          // column group
    const int l = blockIdx.x * 2 + half;

    __shared__ int s01[2][64], s2[2][64];
    if (lane < 64) {
        int s = lane >> 5, b = lane & 31;
        int off = b * PP + l;
        int i0 = (s ? tg0 : in0)[off];
        int i1 = (s ? tg1 : in1)[off];
        int i2 = (s ? tg2 : in2)[off];
        s01[half][lane] = i0 * 24 + i1;
        s2[half][lane]  = i2;
    }

    const float4 tp = *reinterpret_cast<const float4*>(g_tab + OTP + (size_t)l * DM + 4 * lane);

    __syncthreads();

    float4* outv = reinterpret_cast<float4*>(out);

    #pragma unroll 4
    for (int p = 0; p < 64; p++) {
        const float4 v01 = *reinterpret_cast<const float4*>(g_tab + OT01 + (size_t)s01[half][p] * DM + 4 * lane);
        const float4 v2  = *reinterpret_cast<const float4*>(g_tab + OT2  + (size_t)s2[half][p]  * DM + 4 * lane);
        float4 o;
        o.x = v01.x + v2.x + tp.x;
        o.y = v01.y + v2.y + tp.y;
        o.z = v01.z + v2.z + tp.z;
        o.w = v01.w + v2.w + tp.w;
        outv[((size_t)p * PP + l) * (DM / 4) + lane] = o;
    }
}

extern "C" void kernel_launch(void* const* d_in, const int* in_sizes, int n_in,
                              void* d_out, int out_size) {
    const int*   in0  = (const int*)d_in[0];
    const int*   tg0  = (const int*)d_in[1];
    const int*   in1  = (const int*)d_in[2];
    const int*   tg1  = (const int*)d_in[3];
    const int*   in2  = (const int*)d_in[4];
    const int*   tg2  = (const int*)d_in[5];
    const float* emb0 = (const float*)d_in[6];
    const float* emb1 = (const float*)d_in[7];
    const float* emb2 = (const float*)d_in[8];
    const float* pe   = (const float*)d_in[9];
    const float* W    = (const float*)d_in[10];
    const float* bias = (const float*)d_in[11];
    float* out = (float*)d_out;

    dim3 ggrid(39, 16);
    table_gemm_kernel<<<ggrid, 64>>>(emb0, emb1, emb2, pe, W, bias);
    fuse01_kernel<<<168, 128>>>();
    gather_kernel<<<1024, 256>>>(in0, tg0, in1, tg1, in2, tg2, out);
}